// round 1
// baseline (speedup 1.0000x reference)
#include <cuda_runtime.h>
#include <math.h>

#define Bb   2
#define Ss   4096
#define DIMd 768
#define Gg   256
#define Hh   4
#define DKk  64
#define SCALEf 0.125f

// ---------------- scratch (device globals: allocation-free) ----------------
__device__ float g_q[Bb * Ss * Gg];
__device__ float g_k[Bb * Ss * Gg];
__device__ float g_v[Bb * Ss * Gg];
__device__ float g_vw[Bb * Ss * Gg];
__device__ float g_att[Bb * Ss * Gg];
__device__ float g_p[(size_t)Bb * Hh * Ss * Ss];       // exp(scores), 536 MB
__device__ float g_part[Bb * Hh * 8 * Ss];             // partial column sums
__device__ float g_winv[Bb * Hh * Ss];                 // 1/denom per column

// ---------------------------------------------------------------------------
// Generic C[M,N] = A[M,K] @ W[N,K]^T + bias.  BM=BN=64, BK=16, 256 thr, 4x4.
// Used for QKV projections (A=x slice, lda=768) and out-proj (lda=256).
// M=8192, N=256, K=256 for all uses; grid = (N/64, M/64).
// ---------------------------------------------------------------------------
__global__ __launch_bounds__(256) void gemm_nt_bias_kernel(
    const float* __restrict__ A, int lda,
    const float* __restrict__ W,     // [N, K] row-major
    const float* __restrict__ bias,  // [N]
    float* __restrict__ C, int ldc, int K)
{
    __shared__ float As[16][68];
    __shared__ float Ws[16][68];
    const int tid = threadIdx.x;
    const int tx = tid & 15;         // n
    const int ty = tid >> 4;         // m
    const int m0 = blockIdx.y * 64;
    const int n0 = blockIdx.x * 64;

    const int r  = tid >> 2;         // 0..63
    const int kc = (tid & 3) * 4;    // 0,4,8,12

    float acc[4][4] = {};

    for (int k0 = 0; k0 < K; k0 += 16) {
        float4 a4 = *reinterpret_cast<const float4*>(&A[(size_t)(m0 + r) * lda + k0 + kc]);
        As[kc + 0][r] = a4.x; As[kc + 1][r] = a4.y;
        As[kc + 2][r] = a4.z; As[kc + 3][r] = a4.w;
        float4 w4 = *reinterpret_cast<const float4*>(&W[(size_t)(n0 + r) * K + k0 + kc]);
        Ws[kc + 0][r] = w4.x; Ws[kc + 1][r] = w4.y;
        Ws[kc + 2][r] = w4.z; Ws[kc + 3][r] = w4.w;
        __syncthreads();

        #pragma unroll
        for (int k = 0; k < 16; k++) {
            float4 av = *reinterpret_cast<const float4*>(&As[k][ty * 4]);
            float4 wv = *reinterpret_cast<const float4*>(&Ws[k][tx * 4]);
            float a[4] = {av.x, av.y, av.z, av.w};
            float w[4] = {wv.x, wv.y, wv.z, wv.w};
            #pragma unroll
            for (int i = 0; i < 4; i++)
                #pragma unroll
                for (int j = 0; j < 4; j++)
                    acc[i][j] += a[i] * w[j];
        }
        __syncthreads();
    }

    #pragma unroll
    for (int i = 0; i < 4; i++) {
        const int m = m0 + ty * 4 + i;
        const int nb = n0 + tx * 4;
        float4 o;
        o.x = acc[i][0] + bias[nb + 0];
        o.y = acc[i][1] + bias[nb + 1];
        o.z = acc[i][2] + bias[nb + 2];
        o.w = acc[i][3] + bias[nb + 3];
        *reinterpret_cast<float4*>(&C[(size_t)m * ldc + nb]) = o;
    }
}

// ---------------------------------------------------------------------------
// P[b,h,i,j] = exp(scale * q_i . k_j).  Per (b,h): M=N=4096, K=64.
// 128x128 tile, K=64 fully in SMEM, 256 threads, 8x8 per thread (split 4+4).
// Dynamic SMEM: 2 * 128*65*4 = 66560 B.
// grid = (32, 32, 8)
// ---------------------------------------------------------------------------
extern __shared__ float s_dyn[];
__global__ __launch_bounds__(256) void scores_exp_kernel(
    const float* __restrict__ Q,
    const float* __restrict__ Kmat,
    float* __restrict__ P)
{
    float (*Qs)[65] = reinterpret_cast<float(*)[65]>(s_dyn);
    float (*Ks)[65] = reinterpret_cast<float(*)[65]>(s_dyn + 128 * 65);

    const int tid = threadIdx.x;
    const int tx = tid & 15;
    const int ty = tid >> 4;
    const int bh = blockIdx.z;
    const int b = bh >> 2, h = bh & 3;
    const int i0 = blockIdx.y * 128;
    const int j0 = blockIdx.x * 128;

    const float* qbase = Q + ((size_t)(b * Ss + i0)) * Gg + h * DKk;
    const float* kbase = Kmat + ((size_t)(b * Ss + j0)) * Gg + h * DKk;

    const int dc = tx * 4;
    const int r0 = ty;
    #pragma unroll
    for (int it = 0; it < 8; it++) {
        const int r = r0 + it * 16;
        float4 q4 = *reinterpret_cast<const float4*>(qbase + (size_t)r * Gg + dc);
        Qs[r][dc + 0] = q4.x; Qs[r][dc + 1] = q4.y;
        Qs[r][dc + 2] = q4.z; Qs[r][dc + 3] = q4.w;
        float4 k4 = *reinterpret_cast<const float4*>(kbase + (size_t)r * Gg + dc);
        Ks[r][dc + 0] = k4.x; Ks[r][dc + 1] = k4.y;
        Ks[r][dc + 2] = k4.z; Ks[r][dc + 3] = k4.w;
    }
    __syncthreads();

    float acc[8][8] = {};
    #pragma unroll 16
    for (int d = 0; d < 64; d++) {
        float a[8], bb[8];
        #pragma unroll
        for (int c = 0; c < 4; c++) {
            a[c]      = Qs[ty * 4 + c][d];
            a[4 + c]  = Qs[64 + ty * 4 + c][d];
            bb[c]     = Ks[tx * 4 + c][d];
            bb[4 + c] = Ks[64 + tx * 4 + c][d];
        }
        #pragma unroll
        for (int i = 0; i < 8; i++)
            #pragma unroll
            for (int j = 0; j < 8; j++)
                acc[i][j] += a[i] * bb[j];
    }

    const size_t pbase = ((size_t)bh * Ss + i0) * Ss + j0;
    #pragma unroll
    for (int i = 0; i < 8; i++) {
        const int mi = (i < 4) ? (ty * 4 + i) : (64 + ty * 4 + (i - 4));
        float* prow = P + pbase + (size_t)mi * Ss;
        float4 o0, o1;
        o0.x = __expf(acc[i][0] * SCALEf);
        o0.y = __expf(acc[i][1] * SCALEf);
        o0.z = __expf(acc[i][2] * SCALEf);
        o0.w = __expf(acc[i][3] * SCALEf);
        o1.x = __expf(acc[i][4] * SCALEf);
        o1.y = __expf(acc[i][5] * SCALEf);
        o1.z = __expf(acc[i][6] * SCALEf);
        o1.w = __expf(acc[i][7] * SCALEf);
        *reinterpret_cast<float4*>(&prow[tx * 4])      = o0;
        *reinterpret_cast<float4*>(&prow[64 + tx * 4]) = o1;
    }
}

// ---------------------------------------------------------------------------
// Partial column sums over i: part[bh, ic, j] = sum_{i in chunk} P[bh, i, j]
// grid = (16, 8, 8); each thread owns one column j within a 512-row chunk.
// ---------------------------------------------------------------------------
__global__ __launch_bounds__(256) void colsum_part_kernel(
    const float* __restrict__ P, float* __restrict__ part)
{
    const int j  = blockIdx.x * 256 + threadIdx.x;
    const int ic = blockIdx.y;
    const int bh = blockIdx.z;
    const float* p = P + (size_t)bh * Ss * Ss + (size_t)ic * 512 * Ss + j;
    float s0 = 0.f, s1 = 0.f, s2 = 0.f, s3 = 0.f;
    for (int i = 0; i < 512; i += 4) {
        s0 += p[0];
        s1 += p[(size_t)Ss];
        s2 += p[(size_t)2 * Ss];
        s3 += p[(size_t)3 * Ss];
        p += (size_t)4 * Ss;
    }
    part[((bh << 3) + ic) * Ss + j] = (s0 + s1) + (s2 + s3);
}

// winv[bh, j] = 1 / sum_c part[bh, c, j].   grid = 128 x 256 threads
__global__ __launch_bounds__(256) void colsum_final_kernel(
    const float* __restrict__ part, float* __restrict__ winv)
{
    const int idx = blockIdx.x * 256 + threadIdx.x;   // bh*Ss + j
    const int bh = idx >> 12;
    const int j  = idx & (Ss - 1);
    float s = 0.f;
    #pragma unroll
    for (int c = 0; c < 8; c++)
        s += part[((bh << 3) + c) * Ss + j];
    winv[idx] = 1.0f / s;
}

// vw[b,j,h,d] = v[b,j,h,d] * winv[b,h,j].   grid = 8192 x 256 threads
__global__ __launch_bounds__(256) void scale_v_kernel(
    const float* __restrict__ v, const float* __restrict__ winv,
    float* __restrict__ vw)
{
    const int idx = blockIdx.x * 256 + threadIdx.x;    // < B*S*G = 2^21
    const int b    = idx >> 20;                        // Ss*Gg = 2^20
    const int srow = (idx >> 8) & (Ss - 1);
    const int h    = (idx >> 6) & 3;
    vw[idx] = v[idx] * winv[((b << 2) + h) * Ss + srow];
}

// ---------------------------------------------------------------------------
// Att[b,i,h,d] = sum_j P[bh,i,j] * vw[b,j,h,d].  Per (b,h): M=4096,N=64,K=4096
// BM=128, BN=64, BK=16, 256 threads, 8x4 per thread.  grid = (32, 8)
// ---------------------------------------------------------------------------
__global__ __launch_bounds__(256) void pv_kernel(
    const float* __restrict__ P,
    const float* __restrict__ Vw,
    float* __restrict__ Att)
{
    __shared__ float Ps[16][132];
    __shared__ float Vs[16][68];

    const int tid = threadIdx.x;
    const int tx = tid & 15;
    const int ty = tid >> 4;
    const int bh = blockIdx.y;
    const int b = bh >> 2, h = bh & 3;
    const int i0 = blockIdx.x * 128;

    const float* pbase = P + ((size_t)bh * Ss + i0) * Ss;
    const float* vbase = Vw + (size_t)b * Ss * Gg + h * DKk;

    float acc[8][4] = {};

    const int pkc = (tid & 3) * 4;   // 0,4,8,12
    const int pr  = tid >> 2;        // 0..63
    const int vr  = tid >> 4;        // 0..15
    const int vc  = (tid & 15) * 4;  // 0..60

    for (int k0 = 0; k0 < Ss; k0 += 16) {
        #pragma unroll
        for (int it = 0; it < 2; it++) {
            const int rr = pr + it * 64;
            float4 p4 = *reinterpret_cast<const float4*>(pbase + (size_t)rr * Ss + k0 + pkc);
            Ps[pkc + 0][rr] = p4.x; Ps[pkc + 1][rr] = p4.y;
            Ps[pkc + 2][rr] = p4.z; Ps[pkc + 3][rr] = p4.w;
        }
        float4 v4 = *reinterpret_cast<const float4*>(vbase + (size_t)(k0 + vr) * Gg + vc);
        Vs[vr][vc + 0] = v4.x; Vs[vr][vc + 1] = v4.y;
        Vs[vr][vc + 2] = v4.z; Vs[vr][vc + 3] = v4.w;
        __syncthreads();

        #pragma unroll
        for (int k = 0; k < 16; k++) {
            float4 a0 = *reinterpret_cast<const float4*>(&Ps[k][ty * 4]);
            float4 a1 = *reinterpret_cast<const float4*>(&Ps[k][64 + ty * 4]);
            float4 b4 = *reinterpret_cast<const float4*>(&Vs[k][tx * 4]);
            float a[8] = {a0.x, a0.y, a0.z, a0.w, a1.x, a1.y, a1.z, a1.w};
            float bb[4] = {b4.x, b4.y, b4.z, b4.w};
            #pragma unroll
            for (int i = 0; i < 8; i++)
                #pragma unroll
                for (int j = 0; j < 4; j++)
                    acc[i][j] += a[i] * bb[j];
        }
        __syncthreads();
    }

    #pragma unroll
    for (int i = 0; i < 8; i++) {
        const int mi = (i < 4) ? (ty * 4 + i) : (64 + ty * 4 + (i - 4));
        float4 o;
        o.x = acc[i][0]; o.y = acc[i][1]; o.z = acc[i][2]; o.w = acc[i][3];
        *reinterpret_cast<float4*>(
            &Att[((size_t)(b * Ss + i0 + mi)) * Gg + h * DKk + tx * 4]) = o;
    }
}

// ---------------------------------------------------------------------------
extern "C" void kernel_launch(void* const* d_in, const int* in_sizes, int n_in,
                              void* d_out, int out_size)
{
    const float* x  = (const float*)d_in[0];
    const float* wq = (const float*)d_in[1];
    const float* bq = (const float*)d_in[2];
    const float* wk = (const float*)d_in[3];
    const float* bk = (const float*)d_in[4];
    const float* wv = (const float*)d_in[5];
    const float* bv = (const float*)d_in[6];
    const float* wo = (const float*)d_in[7];
    const float* bo = (const float*)d_in[8];
    float* out = (float*)d_out;

    float *q, *k, *v, *vw, *att, *p, *part, *winv;
    cudaGetSymbolAddress((void**)&q,    g_q);
    cudaGetSymbolAddress((void**)&k,    g_k);
    cudaGetSymbolAddress((void**)&v,    g_v);
    cudaGetSymbolAddress((void**)&vw,   g_vw);
    cudaGetSymbolAddress((void**)&att,  g_att);
    cudaGetSymbolAddress((void**)&p,    g_p);
    cudaGetSymbolAddress((void**)&part, g_part);
    cudaGetSymbolAddress((void**)&winv, g_winv);

    const int SCORES_SMEM = 2 * 128 * 65 * 4;   // 66560 B
    cudaFuncSetAttribute(scores_exp_kernel,
                         cudaFuncAttributeMaxDynamicSharedMemorySize, SCORES_SMEM);

    dim3 gProj(4, 128);   // N/64, M/64 for M=8192, N=256

    // 1) QKV projections
    gemm_nt_bias_kernel<<<gProj, 256>>>(x,          DIMd, wq, bq, q, Gg, Gg);
    gemm_nt_bias_kernel<<<gProj, 256>>>(x + Gg,     DIMd, wk, bk, k, Gg, Gg);
    gemm_nt_bias_kernel<<<gProj, 256>>>(x + 2 * Gg, DIMd, wv, bv, v, Gg, Gg);

    // 2) P = exp(scale * Q K^T)
    scores_exp_kernel<<<dim3(32, 32, 8), 256, SCORES_SMEM>>>(q, k, p);

    // 3) column sums over i -> winv
    colsum_part_kernel<<<dim3(16, 8, 8), 256>>>(p, part);
    colsum_final_kernel<<<128, 256>>>(part, winv);

    // 4) vw = v * winv
    scale_v_kernel<<<8192, 256>>>(v, winv, vw);

    // 5) Att = P @ vw
    pv_kernel<<<dim3(32, 8), 256>>>(p, vw, att);

    // 6) out = Att @ wo^T + bo
    gemm_nt_bias_kernel<<<gProj, 256>>>(att, Gg, wo, bo, out, Gg, Gg);
}